// round 3
// baseline (speedup 1.0000x reference)
#include <cuda_runtime.h>
#include <cstdint>

#define N_NODE 100000
#define N_NETS 20000
#define NEDGE  200000
// H_NODE=64, H_NET=32, H_PIN=16, O_NODE=32, O_NET=64

// ---------------- scratch (device globals; no runtime allocation) ----------------
__device__ __align__(16) float g_T[N_NETS * 512];    // [n][p*32+o]  41MB, L2-resident
__device__ __align__(16) float g_Bias[N_NETS * 32];  // [n][o] = sum_i nf[n,i]*b2[i,o]
__device__ __align__(16) float g_agg[N_NETS * 64];
__device__ __align__(16) float g_degN[N_NODE];
__device__ __align__(16) int   g_cnt[N_NETS];        // in-degree per net (int)
__device__ __align__(16) int   g_cursor[N_NETS];
__device__ __align__(16) int   g_start[N_NETS];      // CSR starts (exclusive scan of cnt)
__device__ __align__(16) int   g_sEdge[NEDGE];       // edge id sorted by net
__device__ __align__(16) int   g_sNode[NEDGE];       // edge_node sorted by net
__device__ __align__(16) int   g_sNet[NEDGE];        // net id per sorted slot
__device__ __align__(16) float g_B[32 * 512];        // W2 rearranged: [i][p*32+o]

__device__ __forceinline__ void red_add_v4(float* addr, float4 v) {
    asm volatile("red.global.add.v4.f32 [%0], {%1, %2, %3, %4};"
                 :: "l"(addr), "f"(v.x), "f"(v.y), "f"(v.z), "f"(v.w)
                 : "memory");
}

// ---------------- zero accumulators (graph replays must re-zero) ----------------
// out node region: 800000 f4 ; g_cnt: 5000 f4 ; g_cursor: 5000 f4 ; g_degN: 25000 f4
__global__ void k_zero(float* __restrict__ out) {
    int i = blockIdx.x * blockDim.x + threadIdx.x;
    float4 z = make_float4(0.f, 0.f, 0.f, 0.f);
    if (i < 800000) { ((float4*)out)[i] = z; return; }
    i -= 800000;
    if (i < 5000)  { ((float4*)g_cnt)[i] = z; return; }
    i -= 5000;
    if (i < 5000)  { ((float4*)g_cursor)[i] = z; return; }
    i -= 5000;
    if (i < 25000) { ((float4*)g_degN)[i] = z; return; }
}

// ---------------- W2 [16,1024] -> g_B [32,512] : g_B[i][p*32+o] = W2[p][i*32+o] ----
__global__ void k_rearr(const float* __restrict__ W2) {
    int idx = blockIdx.x * blockDim.x + threadIdx.x;
    if (idx < 16384) {
        int i = idx >> 9;
        int c = idx & 511;
        int p = c >> 5, o = c & 31;
        g_B[idx] = W2[p * 1024 + i * 32 + o];
    }
}

// ---------------- degree counts ----------------
__global__ void k_deg(const int* __restrict__ edge_node, const int* __restrict__ edge_net) {
    int e = blockIdx.x * blockDim.x + threadIdx.x;
    if (e >= NEDGE) return;
    atomicAdd(&g_degN[edge_node[e]], 1.0f);
    atomicAdd(&g_cnt[edge_net[e]], 1);
}

// ---------------- single-block exclusive scan of g_cnt -> g_start ----------------
// 1024 threads x 20 chunk = 20480 >= N_NETS. dyn smem: 20480 ints + 32 ints.
__global__ void __launch_bounds__(1024) k_scan() {
    extern __shared__ int ss[];
    int* wsum = ss + 20480;
    int t = threadIdx.x;
    for (int i = t; i < 20480; i += 1024) ss[i] = (i < N_NETS) ? g_cnt[i] : 0;
    __syncthreads();
    int base = t * 20;
    int sum = 0;
#pragma unroll
    for (int k = 0; k < 20; k++) sum += ss[base + k];
    int lane = t & 31, wid = t >> 5;
    int v = sum;
#pragma unroll
    for (int d = 1; d < 32; d <<= 1) {
        int u = __shfl_up_sync(0xffffffffu, v, d);
        if (lane >= d) v += u;
    }
    if (lane == 31) wsum[wid] = v;   // inclusive warp total
    __syncthreads();
    if (wid == 0) {
        int w = wsum[lane];
#pragma unroll
        for (int d = 1; d < 32; d <<= 1) {
            int u = __shfl_up_sync(0xffffffffu, w, d);
            if (lane >= d) w += u;
        }
        wsum[lane] = w;              // inclusive
    }
    __syncthreads();
    int run = (v - sum) + (wid ? wsum[wid - 1] : 0);  // exclusive prefix for chunk
#pragma unroll
    for (int k = 0; k < 20; k++) {
        int c = ss[base + k];
        ss[base + k] = run;
        run += c;
    }
    __syncthreads();
    for (int i = t; i < N_NETS; i += 1024) g_start[i] = ss[i];
}

// ---------------- counting-sort scatter: edges grouped by net ----------------
__global__ void k_scatter(const int* __restrict__ edge_node, const int* __restrict__ edge_net) {
    int e = blockIdx.x * blockDim.x + threadIdx.x;
    if (e >= NEDGE) return;
    int n = edge_net[e];
    int pos = g_start[n] + atomicAdd(&g_cursor[n], 1);
    g_sEdge[pos] = e;
    g_sNode[pos] = edge_node[e];
    g_sNet[pos]  = n;
}

// ---------------- g_Bias[n][o] = sum_i nf[n,i] * b2[i,o] ----------------
__global__ void __launch_bounds__(256) k_bias(const float* __restrict__ net_feat,
                                              const float* __restrict__ b2) {
    __shared__ float b2s[1024];
    int t = threadIdx.x;
    for (int k = t; k < 1024; k += 256) b2s[k] = b2[k];
    __syncthreads();
    int idx = blockIdx.x * 256 + t;
    int n = idx >> 5, o = idx & 31;
    if (n >= N_NETS) return;
    float acc = 0.f;
#pragma unroll
    for (int i = 0; i < 32; i++) acc += net_feat[n * 32 + i] * b2s[i * 32 + o];
    g_Bias[n * 32 + o] = acc;
}

// ---------------- T GEMM via packed f32x2 FMA ----------------
// block 256 = 128 f4-cols x 2 row-groups; each thread: 8 rows x 1 f4-col.
// 1250 blocks x 16 rows. dyn smem: B 64KB + nf packed 4KB = 69632B.
__global__ void __launch_bounds__(256) k_T(const float* __restrict__ net_feat) {
    extern __shared__ float sm[];
    float* Bs = sm;                           // 16384 floats
    float2* nfp = (float2*)(sm + 16384);      // [i][r] duplicated-packed, 512 float2
    int t = threadIdx.x;

    for (int k = t; k < 4096; k += 256)
        ((float4*)Bs)[k] = ((const float4*)g_B)[k];
    int n0 = blockIdx.x * 16;
    for (int k = t; k < 512; k += 256) {
        int i = k & 31, r = k >> 5;
        float s = net_feat[(n0 + r) * 32 + i];
        nfp[i * 16 + r] = make_float2(s, s);
    }
    __syncthreads();

    int c = t & 127;   // float4 column
    int rg = t >> 7;   // row group 0/1
    const float4* B4 = (const float4*)Bs;

    unsigned long long acc[16];
#pragma unroll
    for (int k = 0; k < 16; k++) acc[k] = 0ull;

#pragma unroll
    for (int i = 0; i < 32; i++) {
        float4 b = B4[i * 128 + c];
        unsigned long long b01, b23;
        asm("mov.b64 %0, {%1, %2};" : "=l"(b01) : "f"(b.x), "f"(b.y));
        asm("mov.b64 %0, {%1, %2};" : "=l"(b23) : "f"(b.z), "f"(b.w));
        const ulonglong2* SPi = (const ulonglong2*)(nfp + i * 16 + rg * 8);
#pragma unroll
        for (int j = 0; j < 4; j++) {
            ulonglong2 sv = SPi[j];
            asm("fma.rn.f32x2 %0, %1, %2, %0;" : "+l"(acc[(2*j)  *2+0]) : "l"(sv.x), "l"(b01));
            asm("fma.rn.f32x2 %0, %1, %2, %0;" : "+l"(acc[(2*j)  *2+1]) : "l"(sv.x), "l"(b23));
            asm("fma.rn.f32x2 %0, %1, %2, %0;" : "+l"(acc[(2*j+1)*2+0]) : "l"(sv.y), "l"(b01));
            asm("fma.rn.f32x2 %0, %1, %2, %0;" : "+l"(acc[(2*j+1)*2+1]) : "l"(sv.y), "l"(b23));
        }
    }

#pragma unroll
    for (int rr = 0; rr < 8; rr++) {
        float4 o;
        asm("mov.b64 {%0, %1}, %2;" : "=f"(o.x), "=f"(o.y) : "l"(acc[rr * 2]));
        asm("mov.b64 {%0, %1}, %2;" : "=f"(o.z), "=f"(o.w) : "l"(acc[rr * 2 + 1]));
        ((float4*)g_T)[(size_t)(n0 + rg * 8 + rr) * 128 + c] = o;
    }
}

// ---------------- relation 1 segment sum: warp per net over CSR ----------------
__global__ void __launch_bounds__(256) k_agg2(const float* __restrict__ node_feat) {
    int w = (blockIdx.x * 256 + threadIdx.x) >> 5;
    int lane = threadIdx.x & 31;
    if (w >= N_NETS) return;
    int start = g_start[w], cnt = g_cnt[w];
    float ax = 0.f, ay = 0.f;
    int p = 0;
    while (p < cnt) {
        int m = min(cnt - p, 32);
        int v = 0; float scl = 0.f;
        if (lane < m) {
            v = g_sNode[start + p + lane];
            scl = rsqrtf(fmaxf(g_degN[v], 1.0f));
        }
        for (int k = 0; k < m; k++) {
            int vv = __shfl_sync(0xffffffffu, v, k);
            float sc = __shfl_sync(0xffffffffu, scl, k);
            float2 x = ((const float2*)node_feat)[vv * 32 + lane];
            ax += sc * x.x;
            ay += sc * x.y;
        }
        p += m;
    }
    float si = rsqrtf(fmaxf((float)cnt, 1.0f));
    ((float2*)g_agg)[w * 32 + lane] = make_float2(ax * si, ay * si);
}

// ---------------- net_out = g_agg @ W1 + b1 (agg already dst-normalized) --------
__global__ void __launch_bounds__(256) k_netout(const float* __restrict__ W1,
                                                const float* __restrict__ b1,
                                                float* __restrict__ net_out) {
    __shared__ float W1s[64 * 64];
    __shared__ float b1s[64];
    int t = threadIdx.x;
    for (int k = t; k < 4096; k += 256) W1s[k] = W1[k];
    if (t < 64) b1s[t] = b1[t];
    __syncthreads();
    int lane = t & 31;
    int n = blockIdx.x * 8 + (t >> 5);
    if (n >= N_NETS) return;
    float a0 = g_agg[n * 64 + lane];
    float a1 = g_agg[n * 64 + 32 + lane];
    float acc0 = b1s[lane], acc1 = b1s[32 + lane];
#pragma unroll
    for (int k = 0; k < 32; k++) {
        float r = __shfl_sync(0xffffffffu, a0, k);
        acc0 += r * W1s[k * 64 + lane];
        acc1 += r * W1s[k * 64 + 32 + lane];
    }
#pragma unroll
    for (int k = 0; k < 32; k++) {
        float r = __shfl_sync(0xffffffffu, a1, k);
        acc0 += r * W1s[(k + 32) * 64 + lane];
        acc1 += r * W1s[(k + 32) * 64 + 32 + lane];
    }
    net_out[n * 64 + lane]      = acc0;
    net_out[n * 64 + 32 + lane] = acc1;
}

// ---------------- relation 2, net-sorted: msg = Bias[n] + pin[e] @ T[n] ----------
// 8 lanes per edge (one float4 of outputs each), 4 sorted edges per warp.
__global__ void __launch_bounds__(256) k_edge(const float* __restrict__ pin_feat,
                                              float* __restrict__ out) {
    int lane = threadIdx.x & 31;
    int warp = (blockIdx.x * 256 + threadIdx.x) >> 5;
    int g = lane >> 3, j = lane & 7;
    int s = warp * 4 + g;
    if (s >= NEDGE) return;
    int n = g_sNet[s];
    int v = g_sNode[s];
    int e = g_sEdge[s];
    const float4* Trow = ((const float4*)g_T) + (size_t)n * 128;
    float4 acc = ((const float4*)g_Bias)[n * 8 + j];
    const float4* pin4 = ((const float4*)pin_feat) + (size_t)e * 4;
#pragma unroll
    for (int q = 0; q < 4; q++) {
        float4 pv = pin4[q];
        float4 t0 = Trow[(4 * q + 0) * 8 + j];
        float4 t1 = Trow[(4 * q + 1) * 8 + j];
        float4 t2 = Trow[(4 * q + 2) * 8 + j];
        float4 t3 = Trow[(4 * q + 3) * 8 + j];
        acc.x += pv.x * t0.x + pv.y * t1.x + pv.z * t2.x + pv.w * t3.x;
        acc.y += pv.x * t0.y + pv.y * t1.y + pv.z * t2.y + pv.w * t3.y;
        acc.z += pv.x * t0.z + pv.y * t1.z + pv.z * t2.z + pv.w * t3.z;
        acc.w += pv.x * t0.w + pv.y * t1.w + pv.z * t2.w + pv.w * t3.w;
    }
    red_add_v4(out + (size_t)v * 32 + j * 4, acc);
}

// ---------------- node_out = accum / clip(degN,1) + b_nn ----------------
__global__ void k_final(const float* __restrict__ b_nn, float* __restrict__ out) {
    int idx = blockIdx.x * blockDim.x + threadIdx.x;
    if (idx >= N_NODE * 8) return;
    int v = idx >> 3, j = idx & 7;
    float inv = 1.0f / fmaxf(g_degN[v], 1.0f);
    float4 o = ((float4*)out)[idx];
    float4 bn = ((const float4*)b_nn)[j];
    o.x = o.x * inv + bn.x;
    o.y = o.y * inv + bn.y;
    o.z = o.z * inv + bn.z;
    o.w = o.w * inv + bn.w;
    ((float4*)out)[idx] = o;
}

extern "C" void kernel_launch(void* const* d_in, const int* in_sizes, int n_in,
                              void* d_out, int out_size) {
    const float* node_feat = (const float*)d_in[0];
    const float* net_feat  = (const float*)d_in[1];
    const float* pin_feat  = (const float*)d_in[2];
    const int*   edge_node = (const int*)d_in[3];
    const int*   edge_net  = (const int*)d_in[4];
    const float* W1   = (const float*)d_in[5];
    const float* b1   = (const float*)d_in[6];
    const float* W2   = (const float*)d_in[7];
    const float* b2   = (const float*)d_in[8];
    const float* b_nn = (const float*)d_in[9];
    float* out = (float*)d_out;

    cudaFuncSetAttribute(k_scan, cudaFuncAttributeMaxDynamicSharedMemorySize, 82048);
    cudaFuncSetAttribute(k_T,    cudaFuncAttributeMaxDynamicSharedMemorySize, 69632);

    k_zero<<<3262, 256>>>(out);
    k_rearr<<<64, 256>>>(W2);
    k_deg<<<782, 256>>>(edge_node, edge_net);
    k_scan<<<1, 1024, 82048>>>();
    k_scatter<<<782, 256>>>(edge_node, edge_net);
    k_bias<<<2500, 256>>>(net_feat, b2);
    k_T<<<1250, 256, 69632>>>(net_feat);
    k_agg2<<<2500, 256>>>(node_feat);
    k_netout<<<2500, 256>>>(W1, b1, out + (size_t)N_NODE * 32);
    k_edge<<<6250, 256>>>(pin_feat, out);
    k_final<<<3125, 256>>>(b_nn, out);
}

// round 4
// speedup vs baseline: 1.0268x; 1.0268x over previous
#include <cuda_runtime.h>
#include <cstdint>

#define N_NODE 100000
#define N_NETS 20000
#define NEDGE  200000
// H_NODE=64, H_NET=32, H_PIN=16, O_NODE=32, O_NET=64

// ---------------- scratch (device globals; no runtime allocation) ----------------
__device__ __align__(16) float g_T[N_NETS * 512];    // [n][p*32+o]  41MB, L2-resident
__device__ __align__(16) float g_Bias[N_NETS * 32];  // [n][o] = sum_i nf[n,i]*b2[i,o]
__device__ __align__(16) float g_agg[N_NETS * 64];   // rel-1 result (normalized)
__device__ __align__(16) float g_degN[N_NODE];
__device__ __align__(16) int   g_cnt[N_NETS];        // in-degree per net
__device__ __align__(16) int   g_cursor[N_NETS];
__device__ __align__(16) int   g_start[N_NETS];      // CSR starts
__device__ __align__(16) int   g_sEdge[NEDGE];       // edge id sorted by net
__device__ __align__(16) int   g_sNode[NEDGE];       // edge_node sorted by net
__device__ __align__(16) float g_B[32 * 512];        // W2 rearranged: [i][p*32+o]

__device__ __forceinline__ void red_add_f32(float* addr, float v) {
    asm volatile("red.global.add.f32 [%0], %1;" :: "l"(addr), "f"(v) : "memory");
}

// ============ 1. zero accumulators (graph replays must re-zero) ============
// out node region: 800000 f4 ; g_cnt: 5000 f4 ; g_cursor: 5000 f4 ; g_degN: 25000 f4
__global__ void k_zero(float* __restrict__ out) {
    int i = blockIdx.x * blockDim.x + threadIdx.x;
    float4 z = make_float4(0.f, 0.f, 0.f, 0.f);
    if (i < 800000) { ((float4*)out)[i] = z; return; }
    i -= 800000;
    if (i < 5000)  { ((float4*)g_cnt)[i] = z; return; }
    i -= 5000;
    if (i < 5000)  { ((float4*)g_cursor)[i] = z; return; }
    i -= 5000;
    if (i < 25000) { ((float4*)g_degN)[i] = z; return; }
}

// ============ 2. degrees + W2 rearrange (independent work, fused) ============
// blocks [0,782): degree atomics.  blocks [782,846): g_B[i][p*32+o] = W2[p][i*32+o]
__global__ void __launch_bounds__(256) k_deg_rearr(const int* __restrict__ edge_node,
                                                   const int* __restrict__ edge_net,
                                                   const float* __restrict__ W2) {
    int b = blockIdx.x;
    int t = threadIdx.x;
    if (b < 782) {
        int e = b * 256 + t;
        if (e >= NEDGE) return;
        atomicAdd(&g_degN[edge_node[e]], 1.0f);
        atomicAdd(&g_cnt[edge_net[e]], 1);
    } else {
        int idx = (b - 782) * 256 + t;
        if (idx < 16384) {
            int i = idx >> 9;
            int c = idx & 511;
            int p = c >> 5, o = c & 31;
            g_B[idx] = W2[p * 1024 + i * 32 + o];
        }
    }
}

// ============ 3. single-block exclusive scan of g_cnt -> g_start ============
// register-resident: 1024 threads x 20 ints each, no big smem array.
__global__ void __launch_bounds__(1024) k_scan() {
    __shared__ int wsum[32];
    int t = threadIdx.x;
    int lane = t & 31, wid = t >> 5;
    int base = t * 20;
    int c[20];
    int sum = 0;
#pragma unroll
    for (int k = 0; k < 20; k++) {
        int i = base + k;
        c[k] = (i < N_NETS) ? g_cnt[i] : 0;
        sum += c[k];
    }
    int v = sum;
#pragma unroll
    for (int d = 1; d < 32; d <<= 1) {
        int u = __shfl_up_sync(0xffffffffu, v, d);
        if (lane >= d) v += u;
    }
    if (lane == 31) wsum[wid] = v;
    __syncthreads();
    if (wid == 0) {
        int w = wsum[lane];
#pragma unroll
        for (int d = 1; d < 32; d <<= 1) {
            int u = __shfl_up_sync(0xffffffffu, w, d);
            if (lane >= d) w += u;
        }
        wsum[lane] = w;
    }
    __syncthreads();
    int run = (v - sum) + (wid ? wsum[wid - 1] : 0);
#pragma unroll
    for (int k = 0; k < 20; k++) {
        int i = base + k;
        if (i < N_NETS) g_start[i] = run;
        run += c[k];
    }
}

// ============ 4. fused mid stage: T GEMM | counting-sort scatter | bias ============
// blocks [0,1250): k_T FFMA2 GEMM (16 net rows/block)
// blocks [1250,2032): scatter edges into net-sorted order
// blocks [2032,4532): g_Bias[n][o] = sum_i nf[n,i]*b2[i,o]
// dyn smem: 69632B (only T blocks use it fully)
__global__ void __launch_bounds__(256) k_mid(const float* __restrict__ net_feat,
                                             const float* __restrict__ b2,
                                             const int* __restrict__ edge_node,
                                             const int* __restrict__ edge_net) {
    extern __shared__ float sm[];
    int b = blockIdx.x;
    int t = threadIdx.x;

    if (b < 1250) {
        // ---- T GEMM via packed f32x2 FMA: 128 f4-cols x 2 row-groups ----
        float* Bs = sm;                           // 16384 floats
        float2* nfp = (float2*)(sm + 16384);      // [i][r] duplicated-packed
        for (int k = t; k < 4096; k += 256)
            ((float4*)Bs)[k] = ((const float4*)g_B)[k];
        int n0 = b * 16;
        for (int k = t; k < 512; k += 256) {
            int i = k & 31, r = k >> 5;
            float s = net_feat[(n0 + r) * 32 + i];
            nfp[i * 16 + r] = make_float2(s, s);
        }
        __syncthreads();

        int c = t & 127;
        int rg = t >> 7;
        const float4* B4 = (const float4*)Bs;

        unsigned long long acc[16];
#pragma unroll
        for (int k = 0; k < 16; k++) acc[k] = 0ull;

#pragma unroll
        for (int i = 0; i < 32; i++) {
            float4 bb = B4[i * 128 + c];
            unsigned long long b01, b23;
            asm("mov.b64 %0, {%1, %2};" : "=l"(b01) : "f"(bb.x), "f"(bb.y));
            asm("mov.b64 %0, {%1, %2};" : "=l"(b23) : "f"(bb.z), "f"(bb.w));
            const ulonglong2* SPi = (const ulonglong2*)(nfp + i * 16 + rg * 8);
#pragma unroll
            for (int j = 0; j < 4; j++) {
                ulonglong2 sv = SPi[j];
                asm("fma.rn.f32x2 %0, %1, %2, %0;" : "+l"(acc[(2*j)  *2+0]) : "l"(sv.x), "l"(b01));
                asm("fma.rn.f32x2 %0, %1, %2, %0;" : "+l"(acc[(2*j)  *2+1]) : "l"(sv.x), "l"(b23));
                asm("fma.rn.f32x2 %0, %1, %2, %0;" : "+l"(acc[(2*j+1)*2+0]) : "l"(sv.y), "l"(b01));
                asm("fma.rn.f32x2 %0, %1, %2, %0;" : "+l"(acc[(2*j+1)*2+1]) : "l"(sv.y), "l"(b23));
            }
        }
#pragma unroll
        for (int rr = 0; rr < 8; rr++) {
            float4 o;
            asm("mov.b64 {%0, %1}, %2;" : "=f"(o.x), "=f"(o.y) : "l"(acc[rr * 2]));
            asm("mov.b64 {%0, %1}, %2;" : "=f"(o.z), "=f"(o.w) : "l"(acc[rr * 2 + 1]));
            ((float4*)g_T)[(size_t)(n0 + rg * 8 + rr) * 128 + c] = o;
        }
    } else if (b < 2032) {
        // ---- counting-sort scatter ----
        int e = (b - 1250) * 256 + t;
        if (e >= NEDGE) return;
        int n = edge_net[e];
        int pos = g_start[n] + atomicAdd(&g_cursor[n], 1);
        g_sEdge[pos] = e;
        g_sNode[pos] = edge_node[e];
    } else {
        // ---- bias: g_Bias[n][o] = sum_i nf[n,i]*b2[i,o] ----
        float* b2s = sm;  // 1024 floats
        for (int k = t; k < 1024; k += 256) b2s[k] = b2[k];
        __syncthreads();
        int idx = (b - 2032) * 256 + t;
        int n = idx >> 5, o = idx & 31;
        if (n >= N_NETS) return;
        float acc = 0.f;
#pragma unroll
        for (int i = 0; i < 32; i++) acc += net_feat[n * 32 + i] * b2s[i * 32 + o];
        g_Bias[n * 32 + o] = acc;
    }
}

// ============ 5. fused edge stage: warp per net ============
// rel-2: msg[e,o] = Bias[n,o] + sum_p pin[e,p]*T[n,p,o]  -> red to out[v*32+o]
// rel-1: ax,ay accumulate node_feat[v]*rsqrt(degN[v])    -> g_agg (normalized)
__global__ void __launch_bounds__(256) k_edge_fused(const float* __restrict__ pin_feat,
                                                    const float* __restrict__ node_feat,
                                                    float* __restrict__ out) {
    int n = (blockIdx.x * 256 + threadIdx.x) >> 5;
    int lane = threadIdx.x & 31;
    if (n >= N_NETS) return;
    int start = g_start[n], cnt = g_cnt[n];

    float Treg[16];
#pragma unroll
    for (int p = 0; p < 16; p++) Treg[p] = g_T[(size_t)n * 512 + p * 32 + lane];
    float bias = g_Bias[n * 32 + lane];

    float ax = 0.f, ay = 0.f;
    const float2* nf2 = (const float2*)node_feat;

    int p0 = 0;
    while (p0 < cnt) {
        int m = min(cnt - p0, 32);
        int v = 0, se = 0; float scl = 0.f;
        if (lane < m) {
            v = g_sNode[start + p0 + lane];
            se = g_sEdge[start + p0 + lane];
            scl = rsqrtf(fmaxf(g_degN[v], 1.0f));
        }
        for (int k = 0; k < m; k += 2) {
            bool two = (k + 1 < m);
            int vA = __shfl_sync(0xffffffffu, v, k);
            int eA = __shfl_sync(0xffffffffu, se, k);
            float sA = __shfl_sync(0xffffffffu, scl, k);
            int vB = __shfl_sync(0xffffffffu, v, k + 1);
            int eB = __shfl_sync(0xffffffffu, se, k + 1);
            float sB = __shfl_sync(0xffffffffu, scl, k + 1);

            // lanes 0-15 carry pin of edge A; lanes 16-31 carry pin of edge B
            int which = lane >> 4;
            float pl = 0.f;
            if (!which)      pl = pin_feat[(size_t)eA * 16 + lane];
            else if (two)    pl = pin_feat[(size_t)eB * 16 + (lane & 15)];

            float msgA = bias, msgB = bias;
#pragma unroll
            for (int q = 0; q < 16; q++) {
                float pA = __shfl_sync(0xffffffffu, pl, q);
                float pB = __shfl_sync(0xffffffffu, pl, 16 + q);
                msgA += pA * Treg[q];
                msgB += pB * Treg[q];
            }
            // rel-1 + rel-2 scatter, edge A
            float2 xA = nf2[(size_t)vA * 32 + lane];
            ax += sA * xA.x;
            ay += sA * xA.y;
            red_add_f32(out + (size_t)vA * 32 + lane, msgA);
            if (two) {
                float2 xB = nf2[(size_t)vB * 32 + lane];
                ax += sB * xB.x;
                ay += sB * xB.y;
                red_add_f32(out + (size_t)vB * 32 + lane, msgB);
            }
        }
        p0 += m;
    }
    float si = rsqrtf(fmaxf((float)cnt, 1.0f));
    ((float2*)g_agg)[n * 32 + lane] = make_float2(ax * si, ay * si);
}

// ============ 6. tail: net_out GEMM | node_out finalize (fused) ============
// blocks [0,2500): net_out = g_agg @ W1 + b1 (warp per net)
// blocks [2500,5625): node_out = accum / clip(degN,1) + b_nn
__global__ void __launch_bounds__(256) k_tail(const float* __restrict__ W1,
                                              const float* __restrict__ b1,
                                              const float* __restrict__ b_nn,
                                              float* __restrict__ out) {
    int b = blockIdx.x;
    int t = threadIdx.x;
    if (b < 2500) {
        __shared__ float W1s[64 * 64];
        __shared__ float b1s[64];
        for (int k = t; k < 4096; k += 256) W1s[k] = W1[k];
        if (t < 64) b1s[t] = b1[t];
        __syncthreads();
        int lane = t & 31;
        int n = b * 8 + (t >> 5);
        if (n >= N_NETS) return;
        float* net_out = out + (size_t)N_NODE * 32;
        float a0 = g_agg[n * 64 + lane];
        float a1 = g_agg[n * 64 + 32 + lane];
        float acc0 = b1s[lane], acc1 = b1s[32 + lane];
#pragma unroll
        for (int k = 0; k < 32; k++) {
            float r = __shfl_sync(0xffffffffu, a0, k);
            acc0 += r * W1s[k * 64 + lane];
            acc1 += r * W1s[k * 64 + 32 + lane];
        }
#pragma unroll
        for (int k = 0; k < 32; k++) {
            float r = __shfl_sync(0xffffffffu, a1, k);
            acc0 += r * W1s[(k + 32) * 64 + lane];
            acc1 += r * W1s[(k + 32) * 64 + 32 + lane];
        }
        net_out[n * 64 + lane]      = acc0;
        net_out[n * 64 + 32 + lane] = acc1;
    } else {
        int idx = (b - 2500) * 256 + t;
        if (idx >= N_NODE * 8) return;
        int v = idx >> 3, j = idx & 7;
        float inv = 1.0f / fmaxf(g_degN[v], 1.0f);
        float4 o = ((float4*)out)[idx];
        float4 bn = ((const float4*)b_nn)[j];
        o.x = o.x * inv + bn.x;
        o.y = o.y * inv + bn.y;
        o.z = o.z * inv + bn.z;
        o.w = o.w * inv + bn.w;
        ((float4*)out)[idx] = o;
    }
}

extern "C" void kernel_launch(void* const* d_in, const int* in_sizes, int n_in,
                              void* d_out, int out_size) {
    const float* node_feat = (const float*)d_in[0];
    const float* net_feat  = (const float*)d_in[1];
    const float* pin_feat  = (const float*)d_in[2];
    const int*   edge_node = (const int*)d_in[3];
    const int*   edge_net  = (const int*)d_in[4];
    const float* W1   = (const float*)d_in[5];
    const float* b1   = (const float*)d_in[6];
    const float* W2   = (const float*)d_in[7];
    const float* b2   = (const float*)d_in[8];
    const float* b_nn = (const float*)d_in[9];
    float* out = (float*)d_out;

    cudaFuncSetAttribute(k_mid, cudaFuncAttributeMaxDynamicSharedMemorySize, 69632);

    k_zero<<<3262, 256>>>(out);
    k_deg_rearr<<<846, 256>>>(edge_node, edge_net, W2);
    k_scan<<<1, 1024>>>();
    k_mid<<<4532, 256, 69632>>>(net_feat, b2, edge_node, edge_net);
    k_edge_fused<<<2500, 256>>>(pin_feat, node_feat, out);
    k_tail<<<5625, 256>>>(W1, b1, b_nn, out);
}

// round 5
// speedup vs baseline: 1.1238x; 1.0945x over previous
#include <cuda_runtime.h>
#include <cstdint>

#define N_NODE 100000
#define N_NETS 20000
#define NEDGE  200000
// H_NODE=64, H_NET=32, H_PIN=16, O_NODE=32, O_NET=64

// ---------------- scratch (device globals; no runtime allocation) ----------------
__device__ __align__(16) float g_T[N_NETS * 512];    // [n][p*32+o]  41MB
__device__ __align__(16) float g_Bias[N_NETS * 32];  // [n][o] = sum_i nf[n,i]*b2[i,o]
__device__ __align__(16) float g_agg[N_NETS * 64];   // rel-1 result (normalized)
__device__ __align__(16) float g_degN[N_NODE];
__device__ __align__(16) int   g_cnt[N_NETS];
__device__ __align__(16) int   g_cursor[N_NETS];
__device__ __align__(16) int   g_start[N_NETS];
__device__ __align__(16) int   g_sEdge[NEDGE];
__device__ __align__(16) int   g_sNode[NEDGE];
__device__ __align__(16) int   g_sNet[NEDGE];
__device__ __align__(16) float g_B[32 * 512];        // W2 rearranged: [i][p*32+o]

__device__ __forceinline__ void red_add_v4(float* addr, float4 v) {
    asm volatile("red.global.add.v4.f32 [%0], {%1, %2, %3, %4};"
                 :: "l"(addr), "f"(v.x), "f"(v.y), "f"(v.z), "f"(v.w)
                 : "memory");
}

// ============ 1. zero accumulators + W2 rearrange ============
// blocks [0,3262): zero out-node region / cnt / cursor / degN
// blocks [3262,3326): g_B[i][p*32+o] = W2[p][i*32+o]
__global__ void __launch_bounds__(256) k_zero_rearr(float* __restrict__ out,
                                                    const float* __restrict__ W2) {
    int b = blockIdx.x;
    if (b < 3262) {
        int i = b * 256 + threadIdx.x;
        float4 z = make_float4(0.f, 0.f, 0.f, 0.f);
        if (i < 800000) { ((float4*)out)[i] = z; return; }
        i -= 800000;
        if (i < 5000)  { ((float4*)g_cnt)[i] = z; return; }
        i -= 5000;
        if (i < 5000)  { ((float4*)g_cursor)[i] = z; return; }
        i -= 5000;
        if (i < 25000) { ((float4*)g_degN)[i] = z; return; }
    } else {
        int idx = (b - 3262) * 256 + threadIdx.x;
        if (idx < 16384) {
            int i = idx >> 9;
            int c = idx & 511;
            int p = c >> 5, o = c & 31;
            g_B[idx] = W2[p * 1024 + i * 32 + o];
        }
    }
}

// ============ 2. degree counts ============
__global__ void k_deg(const int* __restrict__ edge_node, const int* __restrict__ edge_net) {
    int e = blockIdx.x * blockDim.x + threadIdx.x;
    if (e >= NEDGE) return;
    atomicAdd(&g_degN[edge_node[e]], 1.0f);
    atomicAdd(&g_cnt[edge_net[e]], 1);
}

// ============ 3. single-block exclusive scan (register-resident) ============
__global__ void __launch_bounds__(1024) k_scan() {
    __shared__ int wsum[32];
    int t = threadIdx.x;
    int lane = t & 31, wid = t >> 5;
    int base = t * 20;
    int c[20];
    int sum = 0;
#pragma unroll
    for (int k = 0; k < 20; k++) {
        int i = base + k;
        c[k] = (i < N_NETS) ? g_cnt[i] : 0;
        sum += c[k];
    }
    int v = sum;
#pragma unroll
    for (int d = 1; d < 32; d <<= 1) {
        int u = __shfl_up_sync(0xffffffffu, v, d);
        if (lane >= d) v += u;
    }
    if (lane == 31) wsum[wid] = v;
    __syncthreads();
    if (wid == 0) {
        int w = wsum[lane];
#pragma unroll
        for (int d = 1; d < 32; d <<= 1) {
            int u = __shfl_up_sync(0xffffffffu, w, d);
            if (lane >= d) w += u;
        }
        wsum[lane] = w;
    }
    __syncthreads();
    int run = (v - sum) + (wid ? wsum[wid - 1] : 0);
#pragma unroll
    for (int k = 0; k < 20; k++) {
        int i = base + k;
        if (i < N_NETS) g_start[i] = run;
        run += c[k];
    }
}

// ============ 4. T GEMM via packed f32x2 FMA (standalone, full regs) ============
// block 256 = 128 f4-cols x 2 row-groups; each thread: 8 rows x 1 f4-col.
// 1250 blocks x 16 rows. dyn smem: B 64KB + nf packed 4KB = 69632B.
__global__ void __launch_bounds__(256) k_T(const float* __restrict__ net_feat) {
    extern __shared__ float sm[];
    float* Bs = sm;                           // 16384 floats
    float2* nfp = (float2*)(sm + 16384);      // [i][r] duplicated-packed
    int t = threadIdx.x;

    for (int k = t; k < 4096; k += 256)
        ((float4*)Bs)[k] = ((const float4*)g_B)[k];
    int n0 = blockIdx.x * 16;
    for (int k = t; k < 512; k += 256) {
        int i = k & 31, r = k >> 5;
        float s = net_feat[(n0 + r) * 32 + i];
        nfp[i * 16 + r] = make_float2(s, s);
    }
    __syncthreads();

    int c = t & 127;
    int rg = t >> 7;
    const float4* B4 = (const float4*)Bs;

    unsigned long long acc[16];
#pragma unroll
    for (int k = 0; k < 16; k++) acc[k] = 0ull;

#pragma unroll
    for (int i = 0; i < 32; i++) {
        float4 b = B4[i * 128 + c];
        unsigned long long b01, b23;
        asm("mov.b64 %0, {%1, %2};" : "=l"(b01) : "f"(b.x), "f"(b.y));
        asm("mov.b64 %0, {%1, %2};" : "=l"(b23) : "f"(b.z), "f"(b.w));
        const ulonglong2* SPi = (const ulonglong2*)(nfp + i * 16 + rg * 8);
#pragma unroll
        for (int j = 0; j < 4; j++) {
            ulonglong2 sv = SPi[j];
            asm("fma.rn.f32x2 %0, %1, %2, %0;" : "+l"(acc[(2*j)  *2+0]) : "l"(sv.x), "l"(b01));
            asm("fma.rn.f32x2 %0, %1, %2, %0;" : "+l"(acc[(2*j)  *2+1]) : "l"(sv.x), "l"(b23));
            asm("fma.rn.f32x2 %0, %1, %2, %0;" : "+l"(acc[(2*j+1)*2+0]) : "l"(sv.y), "l"(b01));
            asm("fma.rn.f32x2 %0, %1, %2, %0;" : "+l"(acc[(2*j+1)*2+1]) : "l"(sv.y), "l"(b23));
        }
    }

#pragma unroll
    for (int rr = 0; rr < 8; rr++) {
        float4 o;
        asm("mov.b64 {%0, %1}, %2;" : "=f"(o.x), "=f"(o.y) : "l"(acc[rr * 2]));
        asm("mov.b64 {%0, %1}, %2;" : "=f"(o.z), "=f"(o.w) : "l"(acc[rr * 2 + 1]));
        ((float4*)g_T)[(size_t)(n0 + rg * 8 + rr) * 128 + c] = o;
    }
}

// ============ 5. counting-sort scatter + bias (fused, homogeneous-light) ============
// blocks [0,782): scatter.  blocks [782,3282): g_Bias[n][o] = sum_i nf[n,i]*b2[i,o]
__global__ void __launch_bounds__(256) k_scatbias(const int* __restrict__ edge_node,
                                                  const int* __restrict__ edge_net,
                                                  const float* __restrict__ net_feat,
                                                  const float* __restrict__ b2) {
    int b = blockIdx.x;
    int t = threadIdx.x;
    if (b < 782) {
        int e = b * 256 + t;
        if (e >= NEDGE) return;
        int n = edge_net[e];
        int pos = g_start[n] + atomicAdd(&g_cursor[n], 1);
        g_sEdge[pos] = e;
        g_sNode[pos] = edge_node[e];
        g_sNet[pos]  = n;
    } else {
        __shared__ float b2s[1024];
        for (int k = t; k < 1024; k += 256) b2s[k] = b2[k];
        __syncthreads();
        int idx = (b - 782) * 256 + t;
        int n = idx >> 5, o = idx & 31;
        if (n >= N_NETS) return;
        float acc = 0.f;
#pragma unroll
        for (int i = 0; i < 32; i++) acc += net_feat[n * 32 + i] * b2s[i * 32 + o];
        g_Bias[n * 32 + o] = acc;
    }
}

// ============ 6. edge (sorted, per-edge parallel, v4 red) + rel-1 segment sum ============
// blocks [0,6250): 4 edges/warp, 8 lanes/edge. blocks [6250,8750): warp-per-net agg.
__global__ void __launch_bounds__(256) k_edgeagg(const float* __restrict__ pin_feat,
                                                 const float* __restrict__ node_feat,
                                                 float* __restrict__ out) {
    int b = blockIdx.x;
    int t = threadIdx.x;
    int lane = t & 31;
    if (b < 6250) {
        int warp = (b * 256 + t) >> 5;
        int g = lane >> 3, j = lane & 7;
        int s = warp * 4 + g;
        if (s >= NEDGE) return;
        int n = g_sNet[s];
        int v = g_sNode[s];
        int e = g_sEdge[s];
        const float4* Trow = ((const float4*)g_T) + (size_t)n * 128;
        float4 acc = ((const float4*)g_Bias)[n * 8 + j];
        const float4* pin4 = ((const float4*)pin_feat) + (size_t)e * 4;
#pragma unroll
        for (int q = 0; q < 4; q++) {
            float4 pv = pin4[q];
            float4 t0 = Trow[(4 * q + 0) * 8 + j];
            float4 t1 = Trow[(4 * q + 1) * 8 + j];
            float4 t2 = Trow[(4 * q + 2) * 8 + j];
            float4 t3 = Trow[(4 * q + 3) * 8 + j];
            acc.x += pv.x * t0.x + pv.y * t1.x + pv.z * t2.x + pv.w * t3.x;
            acc.y += pv.x * t0.y + pv.y * t1.y + pv.z * t2.y + pv.w * t3.y;
            acc.z += pv.x * t0.z + pv.y * t1.z + pv.z * t2.z + pv.w * t3.z;
            acc.w += pv.x * t0.w + pv.y * t1.w + pv.z * t2.w + pv.w * t3.w;
        }
        red_add_v4(out + (size_t)v * 32 + j * 4, acc);
    } else {
        int n = ((b - 6250) * 256 + t) >> 5;
        if (n >= N_NETS) return;
        int start = g_start[n], cnt = g_cnt[n];
        float ax = 0.f, ay = 0.f;
        const float2* nf2 = (const float2*)node_feat;
        int p = 0;
        while (p < cnt) {
            int m = min(cnt - p, 32);
            int v = 0; float scl = 0.f;
            if (lane < m) {
                v = g_sNode[start + p + lane];
                scl = rsqrtf(fmaxf(g_degN[v], 1.0f));
            }
            for (int k = 0; k < m; k++) {
                int vv = __shfl_sync(0xffffffffu, v, k);
                float sc = __shfl_sync(0xffffffffu, scl, k);
                float2 x = nf2[(size_t)vv * 32 + lane];
                ax += sc * x.x;
                ay += sc * x.y;
            }
            p += m;
        }
        float si = rsqrtf(fmaxf((float)cnt, 1.0f));
        ((float2*)g_agg)[n * 32 + lane] = make_float2(ax * si, ay * si);
    }
}

// ============ 7. tail: net_out GEMM | node_out finalize ============
__global__ void __launch_bounds__(256) k_tail(const float* __restrict__ W1,
                                              const float* __restrict__ b1,
                                              const float* __restrict__ b_nn,
                                              float* __restrict__ out) {
    int b = blockIdx.x;
    int t = threadIdx.x;
    if (b < 2500) {
        __shared__ float W1s[64 * 64];
        __shared__ float b1s[64];
        for (int k = t; k < 4096; k += 256) W1s[k] = W1[k];
        if (t < 64) b1s[t] = b1[t];
        __syncthreads();
        int lane = t & 31;
        int n = b * 8 + (t >> 5);
        if (n >= N_NETS) return;
        float* net_out = out + (size_t)N_NODE * 32;
        float a0 = g_agg[n * 64 + lane];
        float a1 = g_agg[n * 64 + 32 + lane];
        float acc0 = b1s[lane], acc1 = b1s[32 + lane];
#pragma unroll
        for (int k = 0; k < 32; k++) {
            float r = __shfl_sync(0xffffffffu, a0, k);
            acc0 += r * W1s[k * 64 + lane];
            acc1 += r * W1s[k * 64 + 32 + lane];
        }
#pragma unroll
        for (int k = 0; k < 32; k++) {
            float r = __shfl_sync(0xffffffffu, a1, k);
            acc0 += r * W1s[(k + 32) * 64 + lane];
            acc1 += r * W1s[(k + 32) * 64 + 32 + lane];
        }
        net_out[n * 64 + lane]      = acc0;
        net_out[n * 64 + 32 + lane] = acc1;
    } else {
        int idx = (b - 2500) * 256 + t;
        if (idx >= N_NODE * 8) return;
        int v = idx >> 3, j = idx & 7;
        float inv = 1.0f / fmaxf(g_degN[v], 1.0f);
        float4 o = ((float4*)out)[idx];
        float4 bn = ((const float4*)b_nn)[j];
        o.x = o.x * inv + bn.x;
        o.y = o.y * inv + bn.y;
        o.z = o.z * inv + bn.z;
        o.w = o.w * inv + bn.w;
        ((float4*)out)[idx] = o;
    }
}

extern "C" void kernel_launch(void* const* d_in, const int* in_sizes, int n_in,
                              void* d_out, int out_size) {
    const float* node_feat = (const float*)d_in[0];
    const float* net_feat  = (const float*)d_in[1];
    const float* pin_feat  = (const float*)d_in[2];
    const int*   edge_node = (const int*)d_in[3];
    const int*   edge_net  = (const int*)d_in[4];
    const float* W1   = (const float*)d_in[5];
    const float* b1   = (const float*)d_in[6];
    const float* W2   = (const float*)d_in[7];
    const float* b2   = (const float*)d_in[8];
    const float* b_nn = (const float*)d_in[9];
    float* out = (float*)d_out;

    cudaFuncSetAttribute(k_T, cudaFuncAttributeMaxDynamicSharedMemorySize, 69632);

    k_zero_rearr<<<3326, 256>>>(out, W2);
    k_deg<<<782, 256>>>(edge_node, edge_net);
    k_scan<<<1, 1024>>>();
    k_T<<<1250, 256, 69632>>>(net_feat);
    k_scatbias<<<3282, 256>>>(edge_node, edge_net, net_feat, b2);
    k_edgeagg<<<8750, 256>>>(pin_feat, node_feat, out);
    k_tail<<<5625, 256>>>(W1, b1, b_nn, out);
}

// round 6
// speedup vs baseline: 1.1656x; 1.0372x over previous
#include <cuda_runtime.h>
#include <cstdint>

#define N_NODE 100000
#define N_NETS 20000
#define NEDGE  200000
// H_NODE=64, H_NET=32, H_PIN=16, O_NODE=32, O_NET=64

// ---------------- scratch (device globals; no runtime allocation) ----------------
__device__ __align__(16) float g_T[N_NETS * 512];    // [n][p*32+o]  41MB
__device__ __align__(16) float g_Bias[N_NETS * 32];  // [n][o] = sum_i nf[n,i]*b2[i,o]
__device__ __align__(16) float g_agg[N_NETS * 64];   // rel-1 result (normalized)
__device__ __align__(16) float g_degN[N_NODE];
__device__ __align__(16) int   g_cnt[N_NETS];
__device__ __align__(16) int   g_cursor[N_NETS];
__device__ __align__(16) int   g_start[N_NETS];
__device__ __align__(16) int   g_sEdge[NEDGE];
__device__ __align__(16) int   g_sNode[NEDGE];
__device__ __align__(16) int   g_sNet[NEDGE];
__device__ __align__(16) float g_B[32 * 512];        // W2 rearranged: [i][p*32+o]

__device__ __forceinline__ void red_add_v4(float* addr, float4 v) {
    asm volatile("red.global.add.v4.f32 [%0], {%1, %2, %3, %4};"
                 :: "l"(addr), "f"(v.x), "f"(v.y), "f"(v.z), "f"(v.w)
                 : "memory");
}

// ============ 1. zero accumulators + W2 rearrange ============
__global__ void __launch_bounds__(256) k_zero_rearr(float* __restrict__ out,
                                                    const float* __restrict__ W2) {
    int b = blockIdx.x;
    if (b < 3262) {
        int i = b * 256 + threadIdx.x;
        float4 z = make_float4(0.f, 0.f, 0.f, 0.f);
        if (i < 800000) { ((float4*)out)[i] = z; return; }
        i -= 800000;
        if (i < 5000)  { ((float4*)g_cnt)[i] = z; return; }
        i -= 5000;
        if (i < 5000)  { ((float4*)g_cursor)[i] = z; return; }
        i -= 5000;
        if (i < 25000) { ((float4*)g_degN)[i] = z; return; }
    } else {
        int idx = (b - 3262) * 256 + threadIdx.x;
        if (idx < 16384) {
            int i = idx >> 9;
            int c = idx & 511;
            int p = c >> 5, o = c & 31;
            g_B[idx] = W2[p * 1024 + i * 32 + o];
        }
    }
}

// ============ 2. degree counts ============
__global__ void k_deg(const int* __restrict__ edge_node, const int* __restrict__ edge_net) {
    int e = blockIdx.x * blockDim.x + threadIdx.x;
    if (e >= NEDGE) return;
    atomicAdd(&g_degN[edge_node[e]], 1.0f);
    atomicAdd(&g_cnt[edge_net[e]], 1);
}

// ============ 3. single-block exclusive scan (register-resident) ============
__global__ void __launch_bounds__(1024) k_scan() {
    __shared__ int wsum[32];
    int t = threadIdx.x;
    int lane = t & 31, wid = t >> 5;
    int base = t * 20;
    int c[20];
    int sum = 0;
#pragma unroll
    for (int k = 0; k < 20; k++) {
        int i = base + k;
        c[k] = (i < N_NETS) ? g_cnt[i] : 0;
        sum += c[k];
    }
    int v = sum;
#pragma unroll
    for (int d = 1; d < 32; d <<= 1) {
        int u = __shfl_up_sync(0xffffffffu, v, d);
        if (lane >= d) v += u;
    }
    if (lane == 31) wsum[wid] = v;
    __syncthreads();
    if (wid == 0) {
        int w = wsum[lane];
#pragma unroll
        for (int d = 1; d < 32; d <<= 1) {
            int u = __shfl_up_sync(0xffffffffu, w, d);
            if (lane >= d) w += u;
        }
        wsum[lane] = w;
    }
    __syncthreads();
    int run = (v - sum) + (wid ? wsum[wid - 1] : 0);
#pragma unroll
    for (int k = 0; k < 20; k++) {
        int i = base + k;
        if (i < N_NETS) g_start[i] = run;
        run += c[k];
    }
}

// ============ 4. fused mid: T GEMM (32 rows/block, 32 acc chains) | scatter | bias ============
// blocks [0,625): T.  blocks [625,1407): scatter.  blocks [1407,3907): bias.
// dyn smem 73728B = B 64KB + nfp 8KB.
__global__ void __launch_bounds__(256, 2) k_mid(const float* __restrict__ net_feat,
                                                const float* __restrict__ b2,
                                                const int* __restrict__ edge_node,
                                                const int* __restrict__ edge_net) {
    extern __shared__ float sm[];
    int b = blockIdx.x;
    int t = threadIdx.x;

    if (b < 625) {
        // ---- T GEMM: 32 net rows per block; thread = 1 f4col x 16 rows ----
        float* Bs = sm;                           // 16384 floats (64KB)
        float2* nfp = (float2*)(sm + 16384);      // [i*32+r] dup-packed (8KB)
        for (int k = t; k < 4096; k += 256)
            ((float4*)Bs)[k] = ((const float4*)g_B)[k];
        int n0 = b * 32;
        for (int k = t; k < 1024; k += 256) {
            int i = k & 31, r = k >> 5;
            float s = net_feat[(n0 + r) * 32 + i];
            nfp[i * 32 + r] = make_float2(s, s);
        }
        __syncthreads();

        int c = t & 127;   // f4 column
        int rg = t >> 7;   // row half: rows rg*16 .. rg*16+15
        const float4* B4 = (const float4*)Bs;

        unsigned long long acc[32];
#pragma unroll
        for (int k = 0; k < 32; k++) acc[k] = 0ull;

#pragma unroll
        for (int i = 0; i < 32; i++) {
            float4 bb = B4[i * 128 + c];
            unsigned long long b01, b23;
            asm("mov.b64 %0, {%1, %2};" : "=l"(b01) : "f"(bb.x), "f"(bb.y));
            asm("mov.b64 %0, {%1, %2};" : "=l"(b23) : "f"(bb.z), "f"(bb.w));
            const ulonglong2* SPi = (const ulonglong2*)(nfp + i * 32 + rg * 16);
#pragma unroll
            for (int j = 0; j < 8; j++) {
                ulonglong2 sv = SPi[j];   // rows 2j, 2j+1 (dup-packed scalars)
                asm("fma.rn.f32x2 %0, %1, %2, %0;" : "+l"(acc[4*j+0]) : "l"(sv.x), "l"(b01));
                asm("fma.rn.f32x2 %0, %1, %2, %0;" : "+l"(acc[4*j+1]) : "l"(sv.x), "l"(b23));
                asm("fma.rn.f32x2 %0, %1, %2, %0;" : "+l"(acc[4*j+2]) : "l"(sv.y), "l"(b01));
                asm("fma.rn.f32x2 %0, %1, %2, %0;" : "+l"(acc[4*j+3]) : "l"(sv.y), "l"(b23));
            }
        }

#pragma unroll
        for (int rr = 0; rr < 16; rr++) {
            float4 o;
            asm("mov.b64 {%0, %1}, %2;" : "=f"(o.x), "=f"(o.y) : "l"(acc[rr * 2]));
            asm("mov.b64 {%0, %1}, %2;" : "=f"(o.z), "=f"(o.w) : "l"(acc[rr * 2 + 1]));
            ((float4*)g_T)[(size_t)(n0 + rg * 16 + rr) * 128 + c] = o;
        }
    } else if (b < 1407) {
        // ---- counting-sort scatter ----
        int e = (b - 625) * 256 + t;
        if (e >= NEDGE) return;
        int n = edge_net[e];
        int pos = g_start[n] + atomicAdd(&g_cursor[n], 1);
        g_sEdge[pos] = e;
        g_sNode[pos] = edge_node[e];
        g_sNet[pos]  = n;
    } else {
        // ---- bias: g_Bias[n][o] = sum_i nf[n,i]*b2[i,o] ----
        float* b2s = sm;  // 1024 floats
        for (int k = t; k < 1024; k += 256) b2s[k] = b2[k];
        __syncthreads();
        int idx = (b - 1407) * 256 + t;
        int n = idx >> 5, o = idx & 31;
        if (n >= N_NETS) return;
        float acc = 0.f;
#pragma unroll
        for (int i = 0; i < 32; i++) acc += net_feat[n * 32 + i] * b2s[i * 32 + o];
        g_Bias[n * 32 + o] = acc;
    }
}

// ============ 5. edge (sorted, per-edge parallel, v4 red) + rel-1 segment sum ============
__global__ void __launch_bounds__(256) k_edgeagg(const float* __restrict__ pin_feat,
                                                 const float* __restrict__ node_feat,
                                                 float* __restrict__ out) {
    int b = blockIdx.x;
    int t = threadIdx.x;
    int lane = t & 31;
    if (b < 6250) {
        int warp = (b * 256 + t) >> 5;
        int g = lane >> 3, j = lane & 7;
        int s = warp * 4 + g;
        if (s >= NEDGE) return;
        int n = g_sNet[s];
        int v = g_sNode[s];
        int e = g_sEdge[s];
        const float4* Trow = ((const float4*)g_T) + (size_t)n * 128;
        float4 acc = ((const float4*)g_Bias)[n * 8 + j];
        const float4* pin4 = ((const float4*)pin_feat) + (size_t)e * 4;
#pragma unroll
        for (int q = 0; q < 4; q++) {
            float4 pv = pin4[q];
            float4 t0 = Trow[(4 * q + 0) * 8 + j];
            float4 t1 = Trow[(4 * q + 1) * 8 + j];
            float4 t2 = Trow[(4 * q + 2) * 8 + j];
            float4 t3 = Trow[(4 * q + 3) * 8 + j];
            acc.x += pv.x * t0.x + pv.y * t1.x + pv.z * t2.x + pv.w * t3.x;
            acc.y += pv.x * t0.y + pv.y * t1.y + pv.z * t2.y + pv.w * t3.y;
            acc.z += pv.x * t0.z + pv.y * t1.z + pv.z * t2.z + pv.w * t3.z;
            acc.w += pv.x * t0.w + pv.y * t1.w + pv.z * t2.w + pv.w * t3.w;
        }
        red_add_v4(out + (size_t)v * 32 + j * 4, acc);
    } else {
        int n = ((b - 6250) * 256 + t) >> 5;
        if (n >= N_NETS) return;
        int start = g_start[n], cnt = g_cnt[n];
        float ax = 0.f, ay = 0.f;
        const float2* nf2 = (const float2*)node_feat;
        int p = 0;
        while (p < cnt) {
            int m = min(cnt - p, 32);
            int v = 0; float scl = 0.f;
            if (lane < m) {
                v = g_sNode[start + p + lane];
                scl = rsqrtf(fmaxf(g_degN[v], 1.0f));
            }
            for (int k = 0; k < m; k++) {
                int vv = __shfl_sync(0xffffffffu, v, k);
                float sc = __shfl_sync(0xffffffffu, scl, k);
                float2 x = nf2[(size_t)vv * 32 + lane];
                ax += sc * x.x;
                ay += sc * x.y;
            }
            p += m;
        }
        float si = rsqrtf(fmaxf((float)cnt, 1.0f));
        ((float2*)g_agg)[n * 32 + lane] = make_float2(ax * si, ay * si);
    }
}

// ============ 6. tail: net_out GEMM | node_out finalize ============
__global__ void __launch_bounds__(256) k_tail(const float* __restrict__ W1,
                                              const float* __restrict__ b1,
                                              const float* __restrict__ b_nn,
                                              float* __restrict__ out) {
    int b = blockIdx.x;
    int t = threadIdx.x;
    if (b < 2500) {
        __shared__ float W1s[64 * 64];
        __shared__ float b1s[64];
        for (int k = t; k < 4096; k += 256) W1s[k] = W1[k];
        if (t < 64) b1s[t] = b1[t];
        __syncthreads();
        int lane = t & 31;
        int n = b * 8 + (t >> 5);
        if (n >= N_NETS) return;
        float* net_out = out + (size_t)N_NODE * 32;
        float a0 = g_agg[n * 64 + lane];
        float a1 = g_agg[n * 64 + 32 + lane];
        float acc0 = b1s[lane], acc1 = b1s[32 + lane];
#pragma unroll
        for (int k = 0; k < 32; k++) {
            float r = __shfl_sync(0xffffffffu, a0, k);
            acc0 += r * W1s[k * 64 + lane];
            acc1 += r * W1s[k * 64 + 32 + lane];
        }
#pragma unroll
        for (int k = 0; k < 32; k++) {
            float r = __shfl_sync(0xffffffffu, a1, k);
            acc0 += r * W1s[(k + 32) * 64 + lane];
            acc1 += r * W1s[(k + 32) * 64 + 32 + lane];
        }
        net_out[n * 64 + lane]      = acc0;
        net_out[n * 64 + 32 + lane] = acc1;
    } else {
        int idx = (b - 2500) * 256 + t;
        if (idx >= N_NODE * 8) return;
        int v = idx >> 3, j = idx & 7;
        float inv = 1.0f / fmaxf(g_degN[v], 1.0f);
        float4 o = ((float4*)out)[idx];
        float4 bn = ((const float4*)b_nn)[j];
        o.x = o.x * inv + bn.x;
        o.y = o.y * inv + bn.y;
        o.z = o.z * inv + bn.z;
        o.w = o.w * inv + bn.w;
        ((float4*)out)[idx] = o;
    }
}

extern "C" void kernel_launch(void* const* d_in, const int* in_sizes, int n_in,
                              void* d_out, int out_size) {
    const float* node_feat = (const float*)d_in[0];
    const float* net_feat  = (const float*)d_in[1];
    const float* pin_feat  = (const float*)d_in[2];
    const int*   edge_node = (const int*)d_in[3];
    const int*   edge_net  = (const int*)d_in[4];
    const float* W1   = (const float*)d_in[5];
    const float* b1   = (const float*)d_in[6];
    const float* W2   = (const float*)d_in[7];
    const float* b2   = (const float*)d_in[8];
    const float* b_nn = (const float*)d_in[9];
    float* out = (float*)d_out;

    cudaFuncSetAttribute(k_mid, cudaFuncAttributeMaxDynamicSharedMemorySize, 73728);

    k_zero_rearr<<<3326, 256>>>(out, W2);
    k_deg<<<782, 256>>>(edge_node, edge_net);
    k_scan<<<1, 1024>>>();
    k_mid<<<3907, 256, 73728>>>(net_feat, b2, edge_node, edge_net);
    k_edgeagg<<<8750, 256>>>(pin_feat, node_feat, out);
    k_tail<<<5625, 256>>>(W1, b1, b_nn, out);
}

// round 8
// speedup vs baseline: 1.1862x; 1.0177x over previous
#include <cuda_runtime.h>
#include <cstdint>

#define N_NODE 100000
#define N_NETS 20000
#define NEDGE  200000
// H_NODE=64, H_NET=32, H_PIN=16, O_NODE=32, O_NET=64

// ---------------- scratch (device globals; zero-init at load) ----------------
// INVARIANT: g_cnt, g_cursor, g_degN are all-zero at kernel_launch entry;
// every call restores this at its end (k_tail), so replays are identical.
__device__ __align__(16) float g_T[N_NETS * 512];    // [n][p*32+o]  41MB
__device__ __align__(16) float g_Bias[N_NETS * 32];
__device__ __align__(16) float g_agg[N_NETS * 64];
__device__ __align__(16) float g_degN[N_NODE];
__device__ __align__(16) int   g_cnt[N_NETS];
__device__ __align__(16) int   g_cursor[N_NETS];
__device__ __align__(16) int   g_start[N_NETS];
__device__ __align__(16) int   g_sEdge[NEDGE];
__device__ __align__(16) int   g_sNode[NEDGE];
__device__ __align__(16) int   g_sNet[NEDGE];
__device__ __align__(16) float g_B[32 * 512];        // W2 rearranged: [i][p*32+o]

__device__ __forceinline__ void red_add_v4(float* addr, float4 v) {
    asm volatile("red.global.add.v4.f32 [%0], {%1, %2, %3, %4};"
                 :: "l"(addr), "f"(v.x), "f"(v.y), "f"(v.z), "f"(v.w)
                 : "memory");
}

// ============ 1. fused: degrees | zero out-region | W2 rearrange ============
// blocks [0,782): degree atomics (cnt/degN zero on entry — invariant)
// blocks [782,3907): zero out node-accum region (poisoned by harness)
// blocks [3907,3971): g_B[i][p*32+o] = W2[p][i*32+o]
__global__ void __launch_bounds__(256) k_degzero(const int* __restrict__ edge_node,
                                                 const int* __restrict__ edge_net,
                                                 const float* __restrict__ W2,
                                                 float* __restrict__ out) {
    int b = blockIdx.x;
    int t = threadIdx.x;
    if (b < 782) {
        int e = b * 256 + t;
        if (e >= NEDGE) return;
        atomicAdd(&g_degN[edge_node[e]], 1.0f);
        atomicAdd(&g_cnt[edge_net[e]], 1);
    } else if (b < 3907) {
        int i = (b - 782) * 256 + t;
        if (i < 800000)
            ((float4*)out)[i] = make_float4(0.f, 0.f, 0.f, 0.f);
    } else {
        int idx = (b - 3907) * 256 + t;
        if (idx < 16384) {
            int i = idx >> 9;
            int c = idx & 511;
            int p = c >> 5, o = c & 31;
            g_B[idx] = W2[p * 1024 + i * 32 + o];
        }
    }
}

// ============ 2. single-block exclusive scan (register-resident) ============
__global__ void __launch_bounds__(1024) k_scan() {
    __shared__ int wsum[32];
    int t = threadIdx.x;
    int lane = t & 31, wid = t >> 5;
    int base = t * 20;
    int c[20];
    int sum = 0;
#pragma unroll
    for (int k = 0; k < 20; k++) {
        int i = base + k;
        c[k] = (i < N_NETS) ? g_cnt[i] : 0;
        sum += c[k];
    }
    int v = sum;
#pragma unroll
    for (int d = 1; d < 32; d <<= 1) {
        int u = __shfl_up_sync(0xffffffffu, v, d);
        if (lane >= d) v += u;
    }
    if (lane == 31) wsum[wid] = v;
    __syncthreads();
    if (wid == 0) {
        int w = wsum[lane];
#pragma unroll
        for (int d = 1; d < 32; d <<= 1) {
            int u = __shfl_up_sync(0xffffffffu, w, d);
            if (lane >= d) w += u;
        }
        wsum[lane] = w;
    }
    __syncthreads();
    int run = (v - sum) + (wid ? wsum[wid - 1] : 0);
#pragma unroll
    for (int k = 0; k < 20; k++) {
        int i = base + k;
        if (i < N_NETS) g_start[i] = run;
        run += c[k];
    }
}

// ============ 3. fused mid: T GEMM (2 f4cols x 8 rows/thread) | scatter | bias ============
// blocks [0,625): T.  blocks [625,1407): scatter.  blocks [1407,3907): bias.
// dyn smem 73728B = B 64KB + nfp 8KB.
__global__ void __launch_bounds__(256, 2) k_mid(const float* __restrict__ net_feat,
                                                const float* __restrict__ b2,
                                                const int* __restrict__ edge_node,
                                                const int* __restrict__ edge_net) {
    extern __shared__ float sm[];
    int b = blockIdx.x;
    int t = threadIdx.x;

    if (b < 625) {
        // ---- T GEMM: 32 net rows per block; thread = 2 f4cols (c, c+64) x 8 rows ----
        float* Bs = sm;                           // 16384 floats (64KB)
        float2* nfp = (float2*)(sm + 16384);      // [i*32+r] dup-packed (8KB)
        for (int k = t; k < 4096; k += 256)
            ((float4*)Bs)[k] = ((const float4*)g_B)[k];
        int n0 = b * 32;
        for (int k = t; k < 1024; k += 256) {
            int i = k & 31, r = k >> 5;
            float s = net_feat[(n0 + r) * 32 + i];
            nfp[i * 32 + r] = make_float2(s, s);
        }
        __syncthreads();

        int c  = t & 63;   // f4 cols c and c+64
        int rg = t >> 6;   // row group 0..3: rows rg*8 .. rg*8+7
        const float4* B4 = (const float4*)Bs;

        unsigned long long acc[32];
#pragma unroll
        for (int k = 0; k < 32; k++) acc[k] = 0ull;

#pragma unroll
        for (int i = 0; i < 32; i++) {
            float4 bA = B4[i * 128 + c];
            float4 bB = B4[i * 128 + 64 + c];
            unsigned long long a01, a23, b01, b23;
            asm("mov.b64 %0, {%1, %2};" : "=l"(a01) : "f"(bA.x), "f"(bA.y));
            asm("mov.b64 %0, {%1, %2};" : "=l"(a23) : "f"(bA.z), "f"(bA.w));
            asm("mov.b64 %0, {%1, %2};" : "=l"(b01) : "f"(bB.x), "f"(bB.y));
            asm("mov.b64 %0, {%1, %2};" : "=l"(b23) : "f"(bB.z), "f"(bB.w));
            const ulonglong2* SPi = (const ulonglong2*)(nfp + i * 32 + rg * 8);
#pragma unroll
            for (int j = 0; j < 4; j++) {
                ulonglong2 sv = SPi[j];   // dup-packed scalars for rows 2j, 2j+1
                asm("fma.rn.f32x2 %0, %1, %2, %0;" : "+l"(acc[(2*j)  *4+0]) : "l"(sv.x), "l"(a01));
                asm("fma.rn.f32x2 %0, %1, %2, %0;" : "+l"(acc[(2*j)  *4+1]) : "l"(sv.x), "l"(a23));
                asm("fma.rn.f32x2 %0, %1, %2, %0;" : "+l"(acc[(2*j)  *4+2]) : "l"(sv.x), "l"(b01));
                asm("fma.rn.f32x2 %0, %1, %2, %0;" : "+l"(acc[(2*j)  *4+3]) : "l"(sv.x), "l"(b23));
                asm("fma.rn.f32x2 %0, %1, %2, %0;" : "+l"(acc[(2*j+1)*4+0]) : "l"(sv.y), "l"(a01));
                asm("fma.rn.f32x2 %0, %1, %2, %0;" : "+l"(acc[(2*j+1)*4+1]) : "l"(sv.y), "l"(a23));
                asm("fma.rn.f32x2 %0, %1, %2, %0;" : "+l"(acc[(2*j+1)*4+2]) : "l"(sv.y), "l"(b01));
                asm("fma.rn.f32x2 %0, %1, %2, %0;" : "+l"(acc[(2*j+1)*4+3]) : "l"(sv.y), "l"(b23));
            }
        }

#pragma unroll
        for (int r = 0; r < 8; r++) {
            float4 o0, o1;
            asm("mov.b64 {%0, %1}, %2;" : "=f"(o0.x), "=f"(o0.y) : "l"(acc[r * 4 + 0]));
            asm("mov.b64 {%0, %1}, %2;" : "=f"(o0.z), "=f"(o0.w) : "l"(acc[r * 4 + 1]));
            asm("mov.b64 {%0, %1}, %2;" : "=f"(o1.x), "=f"(o1.y) : "l"(acc[r * 4 + 2]));
            asm("mov.b64 {%0, %1}, %2;" : "=f"(o1.z), "=f"(o1.w) : "l"(acc[r * 4 + 3]));
            size_t row = (size_t)(n0 + rg * 8 + r) * 128;
            ((float4*)g_T)[row + c]      = o0;
            ((float4*)g_T)[row + 64 + c] = o1;
        }
    } else if (b < 1407) {
        // ---- counting-sort scatter (cursor zero on entry — invariant) ----
        int e = (b - 625) * 256 + t;
        if (e >= NEDGE) return;
        int n = edge_net[e];
        int pos = g_start[n] + atomicAdd(&g_cursor[n], 1);
        g_sEdge[pos] = e;
        g_sNode[pos] = edge_node[e];
        g_sNet[pos]  = n;
    } else {
        // ---- bias: g_Bias[n][o] = sum_i nf[n,i]*b2[i,o] ----
        float* b2s = sm;  // 1024 floats
        for (int k = t; k < 1024; k += 256) b2s[k] = b2[k];
        __syncthreads();
        int idx = (b - 1407) * 256 + t;
        int n = idx >> 5, o = idx & 31;
        if (n >= N_NETS) return;
        float acc = 0.f;
#pragma unroll
        for (int i = 0; i < 32; i++) acc += net_feat[n * 32 + i] * b2s[i * 32 + o];
        g_Bias[n * 32 + o] = acc;
    }
}

// ============ 4. edge (sorted, per-edge parallel, v4 red) + rel-1 segment sum ============
__global__ void __launch_bounds__(256) k_edgeagg(const float* __restrict__ pin_feat,
                                                 const float* __restrict__ node_feat,
                                                 float* __restrict__ out) {
    int b = blockIdx.x;
    int t = threadIdx.x;
    int lane = t & 31;
    if (b < 6250) {
        int warp = (b * 256 + t) >> 5;
        int g = lane >> 3, j = lane & 7;
        int s = warp * 4 + g;
        if (s >= NEDGE) return;
        int n = g_sNet[s];
        int v = g_sNode[s];
        int e = g_sEdge[s];
        const float4* Trow = ((const float4*)g_T) + (size_t)n * 128;
        float4 acc = ((const float4*)g_Bias)[n * 8 + j];
        const float4* pin4 = ((const float4*)pin_feat) + (size_t)e * 4;
#pragma unroll
        for (int q = 0; q < 4; q++) {
            float4 pv = pin4[q];
            float4 t0 = Trow[(4 * q + 0) * 8 + j];
            float4 t1 = Trow[(4 * q + 1) * 8 + j];
            float4 t2 = Trow[(4 * q + 2) * 8 + j];
            float4 t3 = Trow[(4 * q + 3) * 8 + j];
            acc.x += pv.x * t0.x + pv.y * t1.x + pv.z * t2.x + pv.w * t3.x;
            acc.y += pv.x * t0.y + pv.y * t1.y + pv.z * t2.y + pv.w * t3.y;
            acc.z += pv.x * t0.z + pv.y * t1.z + pv.z * t2.z + pv.w * t3.z;
            acc.w += pv.x * t0.w + pv.y * t1.w + pv.z * t2.w + pv.w * t3.w;
        }
        red_add_v4(out + (size_t)v * 32 + j * 4, acc);
    } else {
        int n = ((b - 6250) * 256 + t) >> 5;
        if (n >= N_NETS) return;
        int start = g_start[n], cnt = g_cnt[n];
        float ax = 0.f, ay = 0.f;
        const float2* nf2 = (const float2*)node_feat;
        int p = 0;
        while (p < cnt) {
            int m = min(cnt - p, 32);
            int v = 0; float scl = 0.f;
            if (lane < m) {
                v = g_sNode[start + p + lane];
                scl = rsqrtf(fmaxf(g_degN[v], 1.0f));
            }
            for (int k = 0; k < m; k++) {
                int vv = __shfl_sync(0xffffffffu, v, k);
                float sc = __shfl_sync(0xffffffffu, scl, k);
                float2 x = nf2[(size_t)vv * 32 + lane];
                ax += sc * x.x;
                ay += sc * x.y;
            }
            p += m;
        }
        float si = rsqrtf(fmaxf((float)cnt, 1.0f));
        ((float2*)g_agg)[n * 32 + lane] = make_float2(ax * si, ay * si);
    }
}

// ============ 5. tail: net_out GEMM | finalize (+restore zero-invariant) ============
// blocks [0,2500): net_out.  blocks [2500,5625): finalize (zero degN after read).
// blocks [5625,5665): zero g_cnt (5000 f4) + g_cursor (5000 f4) for next replay.
__global__ void __launch_bounds__(256) k_tail(const float* __restrict__ W1,
                                              const float* __restrict__ b1,
                                              const float* __restrict__ b_nn,
                                              float* __restrict__ out) {
    int b = blockIdx.x;
    int t = threadIdx.x;
    if (b < 2500) {
        __shared__ float W1s[64 * 64];
        __shared__ float b1s[64];
        for (int k = t; k < 4096; k += 256) W1s[k] = W1[k];
        if (t < 64) b1s[t] = b1[t];
        __syncthreads();
        int lane = t & 31;
        int n = b * 8 + (t >> 5);
        if (n >= N_NETS) return;
        float* net_out = out + (size_t)N_NODE * 32;
        float a0 = g_agg[n * 64 + lane];
        float a1 = g_agg[n * 64 + 32 + lane];
        float acc0 = b1s[lane], acc1 = b1s[32 + lane];
#pragma unroll
        for (int k = 0; k < 32; k++) {
            float r = __shfl_sync(0xffffffffu, a0, k);
            acc0 += r * W1s[k * 64 + lane];
            acc1 += r * W1s[k * 64 + 32 + lane];
        }
#pragma unroll
        for (int k = 0; k < 32; k++) {
            float r = __shfl_sync(0xffffffffu, a1, k);
            acc0 += r * W1s[(k + 32) * 64 + lane];
            acc1 += r * W1s[(k + 32) * 64 + 32 + lane];
        }
        net_out[n * 64 + lane]      = acc0;
        net_out[n * 64 + 32 + lane] = acc1;
    } else if (b < 5625) {
        int idx = (b - 2500) * 256 + t;
        if (idx >= N_NODE * 8) return;
        int v = idx >> 3, j = idx & 7;
        // warp-convergent load of degN[v] strictly precedes the j==0 store
        float dn = g_degN[v];
        float inv = 1.0f / fmaxf(dn, 1.0f);
        float4 o = ((float4*)out)[idx];
        float4 bn = ((const float4*)b_nn)[j];
        o.x = o.x * inv + bn.x;
        o.y = o.y * inv + bn.y;
        o.z = o.z * inv + bn.z;
        o.w = o.w * inv + bn.w;
        ((float4*)out)[idx] = o;
        if (j == 0) g_degN[v] = 0.0f;   // restore invariant for next call
    } else {
        // g_cnt: 20000 ints = 5000 f4 ; g_cursor: same. 40 blocks x 256 = 10240 thr.
        int i = (b - 5625) * 256 + t;
        float4 z = make_float4(0.f, 0.f, 0.f, 0.f);
        if (i < 5000)       ((float4*)g_cnt)[i] = z;
        else if (i < 10000) ((float4*)g_cursor)[i - 5000] = z;
    }
}

extern "C" void kernel_launch(void* const* d_in, const int* in_sizes, int n_in,
                              void* d_out, int out_size) {
    const float* node_feat = (const float*)d_in[0];
    const float* net_feat  = (const float*)d_in[1];
    const float* pin_feat  = (const float*)d_in[2];
    const int*   edge_node = (const int*)d_in[3];
    const int*   edge_net  = (const int*)d_in[4];
    const float* W1   = (const float*)d_in[5];
    const float* b1   = (const float*)d_in[6];
    const float* W2   = (const float*)d_in[7];
    const float* b2   = (const float*)d_in[8];
    const float* b_nn = (const float*)d_in[9];
    float* out = (float*)d_out;

    cudaFuncSetAttribute(k_mid, cudaFuncAttributeMaxDynamicSharedMemorySize, 73728);

    k_degzero<<<3971, 256>>>(edge_node, edge_net, W2, out);
    k_scan<<<1, 1024>>>();
    k_mid<<<3907, 256, 73728>>>(net_feat, b2, edge_node, edge_net);
    k_edgeagg<<<8750, 256>>>(pin_feat, node_feat, out);
    k_tail<<<5665, 256>>>(W1, b1, b_nn, out);
}

// round 9
// speedup vs baseline: 1.2431x; 1.0480x over previous
#include <cuda_runtime.h>
#include <cstdint>

#define N_NODE 100000
#define N_NETS 20000
#define NEDGE  200000
// H_NODE=64, H_NET=32, H_PIN=16, O_NODE=32, O_NET=64

// ---------------- scratch (device globals; zero-init at load) ----------------
// INVARIANT: g_cnt, g_cursor, g_degN are all-zero at kernel_launch entry;
// every call restores this at its end (k_tail), so replays are identical.
__device__ __align__(16) float g_T[N_NETS * 512];    // [n][p*32+o]  41MB
__device__ __align__(16) float g_Bias[N_NETS * 32];
__device__ __align__(16) float g_agg[N_NETS * 64];
__device__ __align__(16) float g_degN[N_NODE];
__device__ __align__(16) int   g_cnt[N_NETS];
__device__ __align__(16) int   g_cursor[N_NETS];
__device__ __align__(16) int   g_start[N_NETS];
__device__ __align__(16) int   g_sEdge[NEDGE];
__device__ __align__(16) int   g_sNode[NEDGE];
__device__ __align__(16) int   g_sNet[NEDGE];
__device__ __align__(16) float g_B[32 * 512];        // W2 rearranged: [i][p*32+o]

__device__ __forceinline__ void red_add_v4(float* addr, float4 v) {
    asm volatile("red.global.add.v4.f32 [%0], {%1, %2, %3, %4};"
                 :: "l"(addr), "f"(v.x), "f"(v.y), "f"(v.z), "f"(v.w)
                 : "memory");
}

// ============ 1. fused: degrees | zero out-region | W2 rearrange | bias ============
// blocks [0,782): degree atomics (cnt/degN zero on entry — invariant)
// blocks [782,3907): zero out node-accum region
// blocks [3907,3971): g_B[i][p*32+o] = W2[p][i*32+o]
// blocks [3971,6471): g_Bias[n][o] = sum_i nf[n,i]*b2[i,o]   (scan-independent)
__global__ void __launch_bounds__(256) k_degzero(const int* __restrict__ edge_node,
                                                 const int* __restrict__ edge_net,
                                                 const float* __restrict__ W2,
                                                 const float* __restrict__ net_feat,
                                                 const float* __restrict__ b2,
                                                 float* __restrict__ out) {
    int b = blockIdx.x;
    int t = threadIdx.x;
    if (b < 782) {
        int e = b * 256 + t;
        if (e >= NEDGE) return;
        atomicAdd(&g_degN[edge_node[e]], 1.0f);
        atomicAdd(&g_cnt[edge_net[e]], 1);
    } else if (b < 3907) {
        int i = (b - 782) * 256 + t;
        if (i < 800000)
            ((float4*)out)[i] = make_float4(0.f, 0.f, 0.f, 0.f);
    } else if (b < 3971) {
        int idx = (b - 3907) * 256 + t;
        if (idx < 16384) {
            int i = idx >> 9;
            int c = idx & 511;
            int p = c >> 5, o = c & 31;
            g_B[idx] = W2[p * 1024 + i * 32 + o];
        }
    } else {
        __shared__ float b2s[1024];
        for (int k = t; k < 1024; k += 256) b2s[k] = b2[k];
        __syncthreads();
        int idx = (b - 3971) * 256 + t;
        int n = idx >> 5, o = idx & 31;
        if (n >= N_NETS) return;
        float acc = 0.f;
#pragma unroll
        for (int i = 0; i < 32; i++) acc += net_feat[n * 32 + i] * b2s[i * 32 + o];
        g_Bias[n * 32 + o] = acc;
    }
}

// ============ 2. single-block exclusive scan (register-resident) ============
__global__ void __launch_bounds__(1024) k_scan() {
    __shared__ int wsum[32];
    int t = threadIdx.x;
    int lane = t & 31, wid = t >> 5;
    int base = t * 20;
    int c[20];
    int sum = 0;
#pragma unroll
    for (int k = 0; k < 20; k++) {
        int i = base + k;
        c[k] = (i < N_NETS) ? g_cnt[i] : 0;
        sum += c[k];
    }
    int v = sum;
#pragma unroll
    for (int d = 1; d < 32; d <<= 1) {
        int u = __shfl_up_sync(0xffffffffu, v, d);
        if (lane >= d) v += u;
    }
    if (lane == 31) wsum[wid] = v;
    __syncthreads();
    if (wid == 0) {
        int w = wsum[lane];
#pragma unroll
        for (int d = 1; d < 32; d <<= 1) {
            int u = __shfl_up_sync(0xffffffffu, w, d);
            if (lane >= d) w += u;
        }
        wsum[lane] = w;
    }
    __syncthreads();
    int run = (v - sum) + (wid ? wsum[wid - 1] : 0);
#pragma unroll
    for (int k = 0; k < 20; k++) {
        int i = base + k;
        if (i < N_NETS) g_start[i] = run;
        run += c[k];
    }
}

// ============ 3. fused mid: T GEMM (regs free, double-buffered B) | scatter ============
// blocks [0,625): T.  blocks [625,1407): scatter.
// dyn smem 73728B = B 64KB + nfp 8KB.
__global__ void __launch_bounds__(256) k_mid(const float* __restrict__ net_feat,
                                             const int* __restrict__ edge_node,
                                             const int* __restrict__ edge_net) {
    extern __shared__ float sm[];
    int b = blockIdx.x;
    int t = threadIdx.x;

    if (b < 625) {
        // ---- T GEMM: 32 net rows per block; thread = 2 f4cols (c, c+64) x 8 rows ----
        float* Bs = sm;                           // 16384 floats (64KB)
        float2* nfp = (float2*)(sm + 16384);      // [i*32+r] dup-packed (8KB)
        for (int k = t; k < 4096; k += 256)
            ((float4*)Bs)[k] = ((const float4*)g_B)[k];
        int n0 = b * 32;
        for (int k = t; k < 1024; k += 256) {
            int i = k & 31, r = k >> 5;
            float s = net_feat[(n0 + r) * 32 + i];
            nfp[i * 32 + r] = make_float2(s, s);
        }
        __syncthreads();

        int c  = t & 63;   // f4 cols c and c+64
        int rg = t >> 6;   // row group 0..3: rows rg*8 .. rg*8+7
        const float4* B4 = (const float4*)Bs;

        unsigned long long acc[32];
#pragma unroll
        for (int k = 0; k < 32; k++) acc[k] = 0ull;

        float4 bA = B4[c];
        float4 bB = B4[64 + c];
#pragma unroll
        for (int i = 0; i < 32; i++) {
            float4 nA = bA, nB = bB;
            if (i < 31) {                         // prefetch next B tile
                nA = B4[(i + 1) * 128 + c];
                nB = B4[(i + 1) * 128 + 64 + c];
            }
            unsigned long long a01, a23, b01, b23;
            asm("mov.b64 %0, {%1, %2};" : "=l"(a01) : "f"(bA.x), "f"(bA.y));
            asm("mov.b64 %0, {%1, %2};" : "=l"(a23) : "f"(bA.z), "f"(bA.w));
            asm("mov.b64 %0, {%1, %2};" : "=l"(b01) : "f"(bB.x), "f"(bB.y));
            asm("mov.b64 %0, {%1, %2};" : "=l"(b23) : "f"(bB.z), "f"(bB.w));
            const ulonglong2* SPi = (const ulonglong2*)(nfp + i * 32 + rg * 8);
            ulonglong2 s0 = SPi[0], s1 = SPi[1], s2 = SPi[2], s3 = SPi[3];
#pragma unroll
            for (int j = 0; j < 4; j++) {
                ulonglong2 sv = (j == 0) ? s0 : (j == 1) ? s1 : (j == 2) ? s2 : s3;
                asm("fma.rn.f32x2 %0, %1, %2, %0;" : "+l"(acc[(2*j)  *4+0]) : "l"(sv.x), "l"(a01));
                asm("fma.rn.f32x2 %0, %1, %2, %0;" : "+l"(acc[(2*j)  *4+1]) : "l"(sv.x), "l"(a23));
                asm("fma.rn.f32x2 %0, %1, %2, %0;" : "+l"(acc[(2*j)  *4+2]) : "l"(sv.x), "l"(b01));
                asm("fma.rn.f32x2 %0, %1, %2, %0;" : "+l"(acc[(2*j)  *4+3]) : "l"(sv.x), "l"(b23));
                asm("fma.rn.f32x2 %0, %1, %2, %0;" : "+l"(acc[(2*j+1)*4+0]) : "l"(sv.y), "l"(a01));
                asm("fma.rn.f32x2 %0, %1, %2, %0;" : "+l"(acc[(2*j+1)*4+1]) : "l"(sv.y), "l"(a23));
                asm("fma.rn.f32x2 %0, %1, %2, %0;" : "+l"(acc[(2*j+1)*4+2]) : "l"(sv.y), "l"(b01));
                asm("fma.rn.f32x2 %0, %1, %2, %0;" : "+l"(acc[(2*j+1)*4+3]) : "l"(sv.y), "l"(b23));
            }
            bA = nA;
            bB = nB;
        }

#pragma unroll
        for (int r = 0; r < 8; r++) {
            float4 o0, o1;
            asm("mov.b64 {%0, %1}, %2;" : "=f"(o0.x), "=f"(o0.y) : "l"(acc[r * 4 + 0]));
            asm("mov.b64 {%0, %1}, %2;" : "=f"(o0.z), "=f"(o0.w) : "l"(acc[r * 4 + 1]));
            asm("mov.b64 {%0, %1}, %2;" : "=f"(o1.x), "=f"(o1.y) : "l"(acc[r * 4 + 2]));
            asm("mov.b64 {%0, %1}, %2;" : "=f"(o1.z), "=f"(o1.w) : "l"(acc[r * 4 + 3]));
            size_t row = (size_t)(n0 + rg * 8 + r) * 128;
            ((float4*)g_T)[row + c]      = o0;
            ((float4*)g_T)[row + 64 + c] = o1;
        }
    } else {
        // ---- counting-sort scatter (cursor zero on entry — invariant) ----
        int e = (b - 625) * 256 + t;
        if (e >= NEDGE) return;
        int n = edge_net[e];
        int pos = g_start[n] + atomicAdd(&g_cursor[n], 1);
        g_sEdge[pos] = e;
        g_sNode[pos] = edge_node[e];
        g_sNet[pos]  = n;
    }
}

// ============ 4. edge (upfront-loaded, high-MLP) + rel-1 segment sum (x4 unroll) ============
__global__ void __launch_bounds__(256) k_edgeagg(const float* __restrict__ pin_feat,
                                                 const float* __restrict__ node_feat,
                                                 float* __restrict__ out) {
    int b = blockIdx.x;
    int t = threadIdx.x;
    int lane = t & 31;
    if (b < 6250) {
        int warp = (b * 256 + t) >> 5;
        int g = lane >> 3, j = lane & 7;
        int s = warp * 4 + g;
        if (s >= NEDGE) return;
        int n = g_sNet[s];
        int v = g_sNode[s];
        int e = g_sEdge[s];
        const float4* Trow = ((const float4*)g_T) + (size_t)n * 128;
        const float4* pin4 = ((const float4*)pin_feat) + (size_t)e * 4;

        // All 21 loads issued upfront -> MLP ~21 per lane
        float4 Treg[16];
#pragma unroll
        for (int q = 0; q < 16; q++) Treg[q] = Trow[q * 8 + j];
        float4 pv[4];
#pragma unroll
        for (int q = 0; q < 4; q++) pv[q] = pin4[q];
        float4 acc = ((const float4*)g_Bias)[n * 8 + j];

#pragma unroll
        for (int q = 0; q < 4; q++) {
            float4 p = pv[q];
            float4 t0 = Treg[4 * q + 0];
            float4 t1 = Treg[4 * q + 1];
            float4 t2 = Treg[4 * q + 2];
            float4 t3 = Treg[4 * q + 3];
            acc.x += p.x * t0.x + p.y * t1.x + p.z * t2.x + p.w * t3.x;
            acc.y += p.x * t0.y + p.y * t1.y + p.z * t2.y + p.w * t3.y;
            acc.z += p.x * t0.z + p.y * t1.z + p.z * t2.z + p.w * t3.z;
            acc.w += p.x * t0.w + p.y * t1.w + p.z * t2.w + p.w * t3.w;
        }
        red_add_v4(out + (size_t)v * 32 + j * 4, acc);
    } else {
        int n = ((b - 6250) * 256 + t) >> 5;
        if (n >= N_NETS) return;
        int start = g_start[n], cnt = g_cnt[n];
        float ax = 0.f, ay = 0.f;
        const float2* nf2 = (const float2*)node_feat;
        int p = 0;
        while (p < cnt) {
            int m = min(cnt - p, 32);
            int v = 0; float scl = 0.f;           // lanes >= m: v=0, scl=0 (safe)
            if (lane < m) {
                v = g_sNode[start + p + lane];
                scl = rsqrtf(fmaxf(g_degN[v], 1.0f));
            }
            int mm = (m + 3) & ~3;                // round up; zero-scl lanes pad
            for (int k = 0; k < mm; k += 4) {
                int v0 = __shfl_sync(0xffffffffu, v, k);
                int v1 = __shfl_sync(0xffffffffu, v, k + 1);
                int v2 = __shfl_sync(0xffffffffu, v, k + 2);
                int v3 = __shfl_sync(0xffffffffu, v, k + 3);
                float s0 = __shfl_sync(0xffffffffu, scl, k);
                float s1 = __shfl_sync(0xffffffffu, scl, k + 1);
                float s2 = __shfl_sync(0xffffffffu, scl, k + 2);
                float s3 = __shfl_sync(0xffffffffu, scl, k + 3);
                float2 x0 = nf2[(size_t)v0 * 32 + lane];
                float2 x1 = nf2[(size_t)v1 * 32 + lane];
                float2 x2 = nf2[(size_t)v2 * 32 + lane];
                float2 x3 = nf2[(size_t)v3 * 32 + lane];
                ax += s0 * x0.x + s1 * x1.x + s2 * x2.x + s3 * x3.x;
                ay += s0 * x0.y + s1 * x1.y + s2 * x2.y + s3 * x3.y;
            }
            p += m;
        }
        float si = rsqrtf(fmaxf((float)cnt, 1.0f));
        ((float2*)g_agg)[n * 32 + lane] = make_float2(ax * si, ay * si);
    }
}

// ============ 5. tail: net_out GEMM | finalize (+restore zero-invariant) ============
// blocks [0,2500): net_out.  blocks [2500,5625): finalize (zero degN after read).
// blocks [5625,5665): zero g_cnt (5000 f4) + g_cursor (5000 f4).
__global__ void __launch_bounds__(256) k_tail(const float* __restrict__ W1,
                                              const float* __restrict__ b1,
                                              const float* __restrict__ b_nn,
                                              float* __restrict__ out) {
    int b = blockIdx.x;
    int t = threadIdx.x;
    if (b < 2500) {
        __shared__ float W1s[64 * 64];
        __shared__ float b1s[64];
        for (int k = t; k < 4096; k += 256) W1s[k] = W1[k];
        if (t < 64) b1s[t] = b1[t];
        __syncthreads();
        int lane = t & 31;
        int n = b * 8 + (t >> 5);
        if (n >= N_NETS) return;
        float* net_out = out + (size_t)N_NODE * 32;
        float a0 = g_agg[n * 64 + lane];
        float a1 = g_agg[n * 64 + 32 + lane];
        float acc0 = b1s[lane], acc1 = b1s[32 + lane];
#pragma unroll
        for (int k = 0; k < 32; k++) {
            float r = __shfl_sync(0xffffffffu, a0, k);
            acc0 += r * W1s[k * 64 + lane];
            acc1 += r * W1s[k * 64 + 32 + lane];
        }
#pragma unroll
        for (int k = 0; k < 32; k++) {
            float r = __shfl_sync(0xffffffffu, a1, k);
            acc0 += r * W1s[(k + 32) * 64 + lane];
            acc1 += r * W1s[(k + 32) * 64 + 32 + lane];
        }
        net_out[n * 64 + lane]      = acc0;
        net_out[n * 64 + 32 + lane] = acc1;
    } else if (b < 5625) {
        int idx = (b - 2500) * 256 + t;
        if (idx >= N_NODE * 8) return;
        int v = idx >> 3, j = idx & 7;
        float dn = g_degN[v];                 // warp-convergent read before j==0 store
        float inv = 1.0f / fmaxf(dn, 1.0f);
        float4 o = ((float4*)out)[idx];
        float4 bn = ((const float4*)b_nn)[j];
        o.x = o.x * inv + bn.x;
        o.y = o.y * inv + bn.y;
        o.z = o.z * inv + bn.z;
        o.w = o.w * inv + bn.w;
        ((float4*)out)[idx] = o;
        if (j == 0) g_degN[v] = 0.0f;         // restore invariant
    } else {
        int i = (b - 5625) * 256 + t;         // 5000 f4 each
        float4 z = make_float4(0.f, 0.f, 0.f, 0.f);
        if (i < 5000)       ((float4*)g_cnt)[i] = z;
        else if (i < 10000) ((float4*)g_cursor)[i - 5000] = z;
    }
}

extern "C" void kernel_launch(void* const* d_in, const int* in_sizes, int n_in,
                              void* d_out, int out_size) {
    const float* node_feat = (const float*)d_in[0];
    const float* net_feat  = (const float*)d_in[1];
    const float* pin_feat  = (const float*)d_in[2];
    const int*   edge_node = (const int*)d_in[3];
    const int*   edge_net  = (const int*)d_in[4];
    const float* W1   = (const float*)d_in[5];
    const float* b1   = (const float*)d_in[6];
    const float* W2   = (const float*)d_in[7];
    const float* b2   = (const float*)d_in[8];
    const float* b_nn = (const float*)d_in[9];
    float* out = (float*)d_out;

    cudaFuncSetAttribute(k_mid, cudaFuncAttributeMaxDynamicSharedMemorySize, 73728);

    k_degzero<<<6471, 256>>>(edge_node, edge_net, W2, net_feat, b2, out);
    k_scan<<<1, 1024>>>();
    k_mid<<<1407, 256, 73728>>>(net_feat, edge_node, edge_net);
    k_edgeagg<<<8750, 256>>>(pin_feat, node_feat, out);
    k_tail<<<5665, 256>>>(W1, b1, b_nn, out);
}